// round 6
// baseline (speedup 1.0000x reference)
#include <cuda_runtime.h>
#include <cuda_fp16.h>
#include <cstdint>

#define N_NODES 8192
#define ALPHA   0.2f

// ---------------- scratch (device globals; no allocations allowed) ----------
__device__ float  g_bufA[N_NODES * 128];
__device__ float  g_bufB[N_NODES * 128];
__device__ float  g_h  [N_NODES * 128];
__device__ __half g_hT [128 * N_NODES];
__device__ float  g_src[N_NODES];
__device__ float  g_dst[N_NODES];
__device__ float  g_zA [N_NODES];
__device__ float  g_zB [N_NODES];
__device__ float  g_gmax[1];

__device__ __forceinline__ float leaky(float x) { return x >= 0.f ? x : ALPHA * x; }

// ---------------------------------------------------------------------------
// GEMM: out[M,128] = act(A[M,K] @ W[K,128] + b). (unchanged)
// ---------------------------------------------------------------------------
__global__ void __launch_bounds__(256, 4) gemm_kernel(
    const float* __restrict__ A, const float* __restrict__ W,
    const float* __restrict__ bias, float* __restrict__ out,
    int K, int do_relu)
{
    __shared__ float As[32][64];
    __shared__ float Ws[64][128];

    const int tid = threadIdx.x;
    const int tx = tid & 31;
    const int ty = tid >> 5;
    const int row0 = blockIdx.x * 32;

    float acc[4][4];
#pragma unroll
    for (int r = 0; r < 4; r++)
#pragma unroll
        for (int c = 0; c < 4; c++) acc[r][c] = 0.f;

    for (int k0 = 0; k0 < K; k0 += 64) {
#pragma unroll
        for (int i = 0; i < 2; i++) {
            int idx = tid + i * 256;
            int r = idx >> 4;
            int c = (idx & 15) << 2;
            *reinterpret_cast<float4*>(&As[r][c]) =
                *reinterpret_cast<const float4*>(&A[(size_t)(row0 + r) * K + k0 + c]);
        }
#pragma unroll
        for (int i = 0; i < 8; i++) {
            int idx = tid + i * 256;
            int r = idx >> 5;
            int c = (idx & 31) << 2;
            *reinterpret_cast<float4*>(&Ws[r][c]) =
                *reinterpret_cast<const float4*>(&W[(size_t)(k0 + r) * 128 + c]);
        }
        __syncthreads();

#pragma unroll 8
        for (int k = 0; k < 64; k++) {
            float4 w = *reinterpret_cast<const float4*>(&Ws[k][tx << 2]);
#pragma unroll
            for (int r = 0; r < 4; r++) {
                float a = As[ty + (r << 3)][k];
                acc[r][0] = fmaf(a, w.x, acc[r][0]);
                acc[r][1] = fmaf(a, w.y, acc[r][1]);
                acc[r][2] = fmaf(a, w.z, acc[r][2]);
                acc[r][3] = fmaf(a, w.w, acc[r][3]);
            }
        }
        __syncthreads();
    }

    float4 bv = *reinterpret_cast<const float4*>(&bias[tx << 2]);
#pragma unroll
    for (int r = 0; r < 4; r++) {
        int row = row0 + ty + (r << 3);
        float4 o;
        o.x = acc[r][0] + bv.x;
        o.y = acc[r][1] + bv.y;
        o.z = acc[r][2] + bv.z;
        o.w = acc[r][3] + bv.w;
        if (do_relu) {
            o.x = fmaxf(o.x, 0.f); o.y = fmaxf(o.y, 0.f);
            o.z = fmaxf(o.z, 0.f); o.w = fmaxf(o.w, 0.f);
        }
        *reinterpret_cast<float4*>(&out[(size_t)row * 128 + (tx << 2)]) = o;
    }
}

// ---------------------------------------------------------------------------
// hT[c][j] fp16  <- h[j][c] f32   (32x32 smem transpose tiles)
// ---------------------------------------------------------------------------
__global__ void __launch_bounds__(256) transpose_kernel(
    const float* __restrict__ h, __half* __restrict__ hT)
{
    __shared__ float tl[32][33];
    int j0 = blockIdx.x * 32, c0 = blockIdx.y * 32;
    int tx = threadIdx.x & 31, ty = threadIdx.x >> 5;
#pragma unroll
    for (int r = 0; r < 4; r++)
        tl[ty + r * 8][tx] = h[(size_t)(j0 + ty + r * 8) * 128 + c0 + tx];
    __syncthreads();
#pragma unroll
    for (int r = 0; r < 4; r++)
        hT[(size_t)(c0 + ty + r * 8) * N_NODES + j0 + tx] =
            __float2half_rn(tl[tx][ty + r * 8]);
}

// ---------------------------------------------------------------------------
// s_src / s_dst, gmax
// ---------------------------------------------------------------------------
__global__ void __launch_bounds__(256) score_kernel(
    const float* __restrict__ h, const float* __restrict__ a_w,
    float* __restrict__ s_src, float* __restrict__ s_dst)
{
    int row = blockIdx.x * 8 + (threadIdx.x >> 5);
    int lane = threadIdx.x & 31;
    float4 hv = *reinterpret_cast<const float4*>(&h[(size_t)row * 128 + lane * 4]);
    float4 a1 = *reinterpret_cast<const float4*>(&a_w[lane * 4]);
    float4 a2 = *reinterpret_cast<const float4*>(&a_w[128 + lane * 4]);
    float d1 = hv.x * a1.x + hv.y * a1.y + hv.z * a1.z + hv.w * a1.w;
    float d2 = hv.x * a2.x + hv.y * a2.y + hv.z * a2.z + hv.w * a2.w;
#pragma unroll
    for (int o = 16; o; o >>= 1) {
        d1 += __shfl_xor_sync(0xffffffffu, d1, o);
        d2 += __shfl_xor_sync(0xffffffffu, d2, o);
    }
    if (lane == 0) { s_src[row] = d1; s_dst[row] = d2; }
}

__global__ void __launch_bounds__(256) gmax_kernel(
    const float* __restrict__ s_dst, float* __restrict__ out)
{
    __shared__ float red[256];
    float m = -1e30f;
    for (int i = threadIdx.x; i < N_NODES; i += 256)
        m = fmaxf(m, s_dst[i]);
    red[threadIdx.x] = m;
    __syncthreads();
    for (int s = 128; s; s >>= 1) {
        if (threadIdx.x < s) red[threadIdx.x] = fmaxf(red[threadIdx.x], red[threadIdx.x + s]);
        __syncthreads();
    }
    if (threadIdx.x == 0) out[0] = red[0];
}

// ---------------------------------------------------------------------------
// mma.sync helpers (base-ISA HMMA path; compiles for compute_103)
// ---------------------------------------------------------------------------
__device__ __forceinline__ void ldsm_x4(unsigned& r0, unsigned& r1,
                                        unsigned& r2, unsigned& r3, unsigned a) {
    asm volatile("ldmatrix.sync.aligned.m8n8.x4.shared.b16 {%0,%1,%2,%3}, [%4];"
                 : "=r"(r0), "=r"(r1), "=r"(r2), "=r"(r3) : "r"(a));
}
__device__ __forceinline__ void mma16816(float* d,
                                         unsigned a0, unsigned a1, unsigned a2, unsigned a3,
                                         unsigned b0, unsigned b1) {
    asm volatile(
        "mma.sync.aligned.m16n8k16.row.col.f32.f16.f16.f32 "
        "{%0,%1,%2,%3}, {%4,%5,%6,%7}, {%8,%9}, {%0,%1,%2,%3};"
        : "+f"(d[0]), "+f"(d[1]), "+f"(d[2]), "+f"(d[3])
        : "r"(a0), "r"(a1), "r"(a2), "r"(a3), "r"(b0), "r"(b1));
}

// ---------------------------------------------------------------------------
// Fused attention via dense HMMA.
// Grid (2 j-halves, 64 row-blocks of M=128), 512 threads (16 warps).
// Per 128-j tile: scatter P (fp16 edge weights, zeros elsewhere) into padded
// smem; cp.async fp16 hT tile; 16 warps do m16n8k16 mma over the 128x128x128
// product, f32 accum in registers. adj for tile k+1 prefetched under mma(k).
// Smem stride 136 halves (272B) -> ldmatrix phases conflict-free.
// ---------------------------------------------------------------------------
#define NTILES 32
#define LDH 136                         // padded row length (halves)
#define HT_BYTES (128 * LDH * 2)        // 34816
#define ATTN_SMEM (4 * HT_BYTES)        // HT0 HT1 P0 P1 = 139264

__global__ void __launch_bounds__(512, 1) attn_kernel(
    const float* __restrict__ adj, const __half* __restrict__ hTg,
    const float* __restrict__ s_src, const float* __restrict__ s_dst,
    const float* __restrict__ p_ab, const float* __restrict__ p_gmax,
    float* __restrict__ accA, float* __restrict__ accB,
    float* __restrict__ zA, float* __restrict__ zB)
{
    extern __shared__ char sm[];
    const unsigned smb = (unsigned)__cvta_generic_to_shared(sm);
    const unsigned HT0 = smb, HT1 = smb + HT_BYTES;
    const unsigned P0 = smb + 2 * HT_BYTES, P1 = smb + 3 * HT_BYTES;

    const int tid = threadIdx.x, wid = tid >> 5, lane = tid & 31;
    const int half = blockIdx.x, r0 = blockIdx.y * 128;
    const int j0 = half * (N_NODES / 2);
    float* accbuf = half ? accB : accA;
    float* zbuf   = half ? zB  : zA;

    // P-build mapping: thread -> (row, 32-j segment)
    const int row = tid >> 2;
    const int q   = tid & 3;
    const float ab   = *p_ab;
    const float gmax = *p_gmax;
    const float si   = s_src[r0 + row];
    const float mi   = leaky(si + ab + gmax);
    float z = 0.f;

    // MMA warp tiling: 8 row-groups x 2 col-groups; warp = 16 rows x 64 cols
    const int wrow = (wid & 7) * 16;
    const int wcol = (wid >> 3) * 64;
    // ldmatrix lane offsets (bytes within P / HT buffers)
    const unsigned a_off = (unsigned)(wrow + (lane & 15)) * (LDH * 2)
                         + (unsigned)((lane >> 4) * 8) * 2;
    const unsigned b_off = (unsigned)(wcol + (lane & 7) + ((lane >> 4) << 3)) * (LDH * 2)
                         + (unsigned)(((lane >> 3) & 1) << 3) * 2;

    float acc[8][4];
#pragma unroll
    for (int f = 0; f < 8; f++)
#pragma unroll
        for (int c = 0; c < 4; c++) acc[f][c] = 0.f;

    const float* arow = adj + (size_t)(r0 + row) * N_NODES + j0 + q * 32;
    const float* tsrc = s_dst + j0 + q * 32;

    auto load_hT = [&](int tile, unsigned Hb) {
#pragma unroll
        for (int i = 0; i < 4; i++) {
            int ch = tid + i * 512;
            int c = ch >> 4, u = ch & 15;
            const __half* src = hTg + (size_t)c * N_NODES + j0 + tile * 128 + u * 8;
            unsigned ad = Hb + (unsigned)c * (LDH * 2) + (unsigned)u * 16;
            asm volatile("cp.async.ca.shared.global [%0], [%1], 16;"
                         :: "r"(ad), "l"(src));
        }
    };

    // prologue: hT tile 0 + adj tile 0
    float4 av[8];
    load_hT(0, HT0);
    asm volatile("cp.async.commit_group;" ::: "memory");
#pragma unroll
    for (int v = 0; v < 8; v++)
        av[v] = *reinterpret_cast<const float4*>(arow + v * 4);

    for (int k = 0; k < NTILES; k++) {
        const unsigned Pb = (k & 1) ? P1 : P0;
        const unsigned Hb = (k & 1) ? HT1 : HT0;

        // ---- build P(k): fp16 weights at edges, zeros elsewhere; z in f32 ----
        unsigned arr[16];
#pragma unroll
        for (int i = 0; i < 16; i++) arr[i] = 0u;
        const float4* t4 = reinterpret_cast<const float4*>(tsrc + k * 128);
#pragma unroll
        for (int v = 0; v < 8; v++) {
            float4 a = av[v];
            bool e0 = a.x >= 0.5f, e1 = a.y >= 0.5f, e2 = a.z >= 0.5f, e3 = a.w >= 0.5f;
            if (e0 | e1 | e2 | e3) {
                float4 t = t4[v];
                if (e0) { float w = __expf(leaky(si + t.x + ab) - mi); z += w;
                          arr[v*2]   |= (unsigned)__half_as_ushort(__float2half_rn(w)); }
                if (e1) { float w = __expf(leaky(si + t.y + ab) - mi); z += w;
                          arr[v*2]   |= (unsigned)__half_as_ushort(__float2half_rn(w)) << 16; }
                if (e2) { float w = __expf(leaky(si + t.z + ab) - mi); z += w;
                          arr[v*2+1] |= (unsigned)__half_as_ushort(__float2half_rn(w)); }
                if (e3) { float w = __expf(leaky(si + t.w + ab) - mi); z += w;
                          arr[v*2+1] |= (unsigned)__half_as_ushort(__float2half_rn(w)) << 16; }
            }
        }
#pragma unroll
        for (int u2 = 0; u2 < 4; u2++) {
            unsigned ad = Pb + (unsigned)row * (LDH * 2)
                        + (unsigned)(q * 32 + u2 * 8) * 2;
            asm volatile("st.shared.v4.b32 [%0], {%1,%2,%3,%4};"
                         :: "r"(ad), "r"(arr[u2*4]), "r"(arr[u2*4+1]),
                            "r"(arr[u2*4+2]), "r"(arr[u2*4+3]) : "memory");
        }

        // ---- wait hT(k), make P visible ----
        asm volatile("cp.async.wait_group 0;" ::: "memory");
        __syncthreads();

        // ---- prefetch tile k+1 (hT via cp.async, adj into regs) ----
        if (k + 1 < NTILES) {
            load_hT(k + 1, (k & 1) ? HT0 : HT1);
            asm volatile("cp.async.commit_group;" ::: "memory");
#pragma unroll
            for (int v = 0; v < 8; v++)
                av[v] = *reinterpret_cast<const float4*>(arow + (k + 1) * 128 + v * 4);
        }

        // ---- dense mma over this tile ----
#pragma unroll
        for (int ks = 0; ks < 8; ks++) {
            unsigned a0, a1, a2, a3;
            ldsm_x4(a0, a1, a2, a3, Pb + a_off + (unsigned)ks * 32);
#pragma unroll
            for (int nb = 0; nb < 4; nb++) {
                unsigned b0, b1, b2, b3;
                ldsm_x4(b0, b1, b2, b3,
                        Hb + b_off + (unsigned)nb * 16 * (LDH * 2) + (unsigned)ks * 32);
                mma16816(acc[nb * 2],     a0, a1, a2, a3, b0, b1);
                mma16816(acc[nb * 2 + 1], a0, a1, a2, a3, b2, b3);
            }
        }
    }

    // ---- epilogue: unnormalized acc to global ----
#pragma unroll
    for (int f = 0; f < 8; f++) {
        int n0 = wcol + f * 8 + (lane & 3) * 2;
        int rr = r0 + wrow + (lane >> 2);
        *reinterpret_cast<float2*>(&accbuf[(size_t)rr * 128 + n0]) =
            make_float2(acc[f][0], acc[f][1]);
        *reinterpret_cast<float2*>(&accbuf[(size_t)(rr + 8) * 128 + n0]) =
            make_float2(acc[f][2], acc[f][3]);
    }
    // z: reduce the 4 q-lanes of each row
    z += __shfl_xor_sync(0xffffffffu, z, 1);
    z += __shfl_xor_sync(0xffffffffu, z, 2);
    if (q == 0) zbuf[r0 + row] = z;
}

// ---------------------------------------------------------------------------
// out = leaky((accA + accB) / (zA + zB))
// ---------------------------------------------------------------------------
__global__ void __launch_bounds__(256) combine_kernel(
    const float* __restrict__ a, const float* __restrict__ b,
    const float* __restrict__ za, const float* __restrict__ zb,
    float* __restrict__ out)
{
    int idx = blockIdx.x * 256 + threadIdx.x;
    int row = idx >> 5;
    float inv = 1.f / (za[row] + zb[row]);
    float4 x = reinterpret_cast<const float4*>(a)[idx];
    float4 y = reinterpret_cast<const float4*>(b)[idx];
    float4 o;
    o.x = leaky((x.x + y.x) * inv);
    o.y = leaky((x.y + y.y) * inv);
    o.z = leaky((x.z + y.z) * inv);
    o.w = leaky((x.w + y.w) * inv);
    reinterpret_cast<float4*>(out)[idx] = o;
}

// ---------------------------------------------------------------------------
extern "C" void kernel_launch(void* const* d_in, const int* in_sizes, int n_in,
                              void* d_out, int out_size)
{
    const float* nodes = (const float*)d_in[0];
    const float* adj   = (const float*)d_in[1];
    const float* W1    = (const float*)d_in[2];
    const float* b1    = (const float*)d_in[3];
    const float* W2    = (const float*)d_in[4];
    const float* b2    = (const float*)d_in[5];
    const float* W3    = (const float*)d_in[6];
    const float* b3    = (const float*)d_in[7];
    const float* W4    = (const float*)d_in[8];
    const float* b4    = (const float*)d_in[9];
    const float* a_w   = (const float*)d_in[10];
    const float* a_b   = (const float*)d_in[11];
    float* out = (float*)d_out;

    float *pA, *pB, *pH, *pSrc, *pDst, *pZA, *pZB, *pGM;
    __half* pHT;
    cudaGetSymbolAddress((void**)&pA,  g_bufA);
    cudaGetSymbolAddress((void**)&pB,  g_bufB);
    cudaGetSymbolAddress((void**)&pH,  g_h);
    cudaGetSymbolAddress((void**)&pHT, g_hT);
    cudaGetSymbolAddress((void**)&pSrc, g_src);
    cudaGetSymbolAddress((void**)&pDst, g_dst);
    cudaGetSymbolAddress((void**)&pZA, g_zA);
    cudaGetSymbolAddress((void**)&pZB, g_zB);
    cudaGetSymbolAddress((void**)&pGM, g_gmax);

    // 4-layer MLP
    gemm_kernel<<<256, 256>>>(nodes, W1, b1, pA, 256, 1);
    gemm_kernel<<<256, 256>>>(pA,    W2, b2, pB, 128, 1);
    gemm_kernel<<<256, 256>>>(pB,    W3, b3, pA, 128, 1);
    gemm_kernel<<<256, 256>>>(pA,    W4, b4, pH, 128, 0);

    // h -> hT (fp16), scores, global max bound
    transpose_kernel<<<dim3(256, 4), 256>>>(pH, pHT);
    score_kernel<<<1024, 256>>>(pH, a_w, pSrc, pDst);
    gmax_kernel<<<1, 256>>>(pDst, pGM);

    // fused attention via dense HMMA
    cudaFuncSetAttribute(attn_kernel,
                         cudaFuncAttributeMaxDynamicSharedMemorySize, ATTN_SMEM);
    dim3 agrid(2, 64);
    attn_kernel<<<agrid, 512, ATTN_SMEM>>>(
        adj, pHT, pSrc, pDst, a_b, pGM, pA, pB, pZA, pZB);

    // normalize + activation
    combine_kernel<<<1024, 256>>>(pA, pB, pZA, pZB, out);
}

// round 7
// speedup vs baseline: 1.1872x; 1.1872x over previous
#include <cuda_runtime.h>
#include <cuda_fp16.h>
#include <cstdint>

#define N_NODES 8192
#define ALPHA   0.2f

// ---------------- scratch (device globals; no allocations allowed) ----------
__device__ float  g_bufA[N_NODES * 128];
__device__ float  g_bufB[N_NODES * 128];
__device__ float  g_h  [N_NODES * 128];
__device__ __half g_hT [128 * N_NODES];
__device__ float  g_src[N_NODES];
__device__ float  g_dst[N_NODES];
__device__ float  g_zA [N_NODES];
__device__ float  g_zB [N_NODES];
__device__ float  g_gmax[1];

__device__ __forceinline__ float leaky(float x) { return x >= 0.f ? x : ALPHA * x; }

// ---------------------------------------------------------------------------
// GEMM: out[M,128] = act(A[M,K] @ W[K,128] + b). 16 rows/block, 512 blocks.
// ---------------------------------------------------------------------------
__global__ void __launch_bounds__(256) gemm_kernel(
    const float* __restrict__ A, const float* __restrict__ W,
    const float* __restrict__ bias, float* __restrict__ out,
    int K, int do_relu)
{
    __shared__ float As[16][64];
    __shared__ float Ws[64][128];

    const int tid = threadIdx.x;
    const int tx = tid & 31;
    const int ty = tid >> 5;
    const int row0 = blockIdx.x * 16;

    float acc[2][4];
#pragma unroll
    for (int r = 0; r < 2; r++)
#pragma unroll
        for (int c = 0; c < 4; c++) acc[r][c] = 0.f;

    for (int k0 = 0; k0 < K; k0 += 64) {
        // A tile: 16x64 = 256 float4, 1 per thread
        {
            int r = tid >> 4;
            int c = (tid & 15) << 2;
            *reinterpret_cast<float4*>(&As[r][c]) =
                *reinterpret_cast<const float4*>(&A[(size_t)(row0 + r) * K + k0 + c]);
        }
        // W tile: 64x128 = 2048 float4, 8 per thread
#pragma unroll
        for (int i = 0; i < 8; i++) {
            int idx = tid + i * 256;
            int r = idx >> 5;
            int c = (idx & 31) << 2;
            *reinterpret_cast<float4*>(&Ws[r][c]) =
                *reinterpret_cast<const float4*>(&W[(size_t)(k0 + r) * 128 + c]);
        }
        __syncthreads();

#pragma unroll 8
        for (int k = 0; k < 64; k++) {
            float4 w = *reinterpret_cast<const float4*>(&Ws[k][tx << 2]);
            float a0 = As[ty][k];
            float a1 = As[ty + 8][k];
            acc[0][0] = fmaf(a0, w.x, acc[0][0]);
            acc[0][1] = fmaf(a0, w.y, acc[0][1]);
            acc[0][2] = fmaf(a0, w.z, acc[0][2]);
            acc[0][3] = fmaf(a0, w.w, acc[0][3]);
            acc[1][0] = fmaf(a1, w.x, acc[1][0]);
            acc[1][1] = fmaf(a1, w.y, acc[1][1]);
            acc[1][2] = fmaf(a1, w.z, acc[1][2]);
            acc[1][3] = fmaf(a1, w.w, acc[1][3]);
        }
        __syncthreads();
    }

    float4 bv = *reinterpret_cast<const float4*>(&bias[tx << 2]);
#pragma unroll
    for (int r = 0; r < 2; r++) {
        int row = row0 + ty + r * 8;
        float4 o;
        o.x = acc[r][0] + bv.x;
        o.y = acc[r][1] + bv.y;
        o.z = acc[r][2] + bv.z;
        o.w = acc[r][3] + bv.w;
        if (do_relu) {
            o.x = fmaxf(o.x, 0.f); o.y = fmaxf(o.y, 0.f);
            o.z = fmaxf(o.z, 0.f); o.w = fmaxf(o.w, 0.f);
        }
        *reinterpret_cast<float4*>(&out[(size_t)row * 128 + (tx << 2)]) = o;
    }
}

// ---------------------------------------------------------------------------
// hT[c][j] fp16  <- h[j][c] f32
// ---------------------------------------------------------------------------
__global__ void __launch_bounds__(256) transpose_kernel(
    const float* __restrict__ h, __half* __restrict__ hT)
{
    __shared__ float tl[32][33];
    int j0 = blockIdx.x * 32, c0 = blockIdx.y * 32;
    int tx = threadIdx.x & 31, ty = threadIdx.x >> 5;
#pragma unroll
    for (int r = 0; r < 4; r++)
        tl[ty + r * 8][tx] = h[(size_t)(j0 + ty + r * 8) * 128 + c0 + tx];
    __syncthreads();
#pragma unroll
    for (int r = 0; r < 4; r++)
        hT[(size_t)(c0 + ty + r * 8) * N_NODES + j0 + tx] =
            __float2half_rn(tl[tx][ty + r * 8]);
}

// ---------------------------------------------------------------------------
// s_src / s_dst, gmax
// ---------------------------------------------------------------------------
__global__ void __launch_bounds__(256) score_kernel(
    const float* __restrict__ h, const float* __restrict__ a_w,
    float* __restrict__ s_src, float* __restrict__ s_dst)
{
    int row = blockIdx.x * 8 + (threadIdx.x >> 5);
    int lane = threadIdx.x & 31;
    float4 hv = *reinterpret_cast<const float4*>(&h[(size_t)row * 128 + lane * 4]);
    float4 a1 = *reinterpret_cast<const float4*>(&a_w[lane * 4]);
    float4 a2 = *reinterpret_cast<const float4*>(&a_w[128 + lane * 4]);
    float d1 = hv.x * a1.x + hv.y * a1.y + hv.z * a1.z + hv.w * a1.w;
    float d2 = hv.x * a2.x + hv.y * a2.y + hv.z * a2.z + hv.w * a2.w;
#pragma unroll
    for (int o = 16; o; o >>= 1) {
        d1 += __shfl_xor_sync(0xffffffffu, d1, o);
        d2 += __shfl_xor_sync(0xffffffffu, d2, o);
    }
    if (lane == 0) { s_src[row] = d1; s_dst[row] = d2; }
}

__global__ void __launch_bounds__(256) gmax_kernel(
    const float* __restrict__ s_dst, float* __restrict__ out)
{
    __shared__ float red[256];
    float m = -1e30f;
    for (int i = threadIdx.x; i < N_NODES; i += 256)
        m = fmaxf(m, s_dst[i]);
    red[threadIdx.x] = m;
    __syncthreads();
    for (int s = 128; s; s >>= 1) {
        if (threadIdx.x < s) red[threadIdx.x] = fmaxf(red[threadIdx.x], red[threadIdx.x + s]);
        __syncthreads();
    }
    if (threadIdx.x == 0) out[0] = red[0];
}

// ---------------------------------------------------------------------------
// mma.sync helpers (base-ISA HMMA path)
// ---------------------------------------------------------------------------
__device__ __forceinline__ void ldsm_x4(unsigned& r0, unsigned& r1,
                                        unsigned& r2, unsigned& r3, unsigned a) {
    asm volatile("ldmatrix.sync.aligned.m8n8.x4.shared.b16 {%0,%1,%2,%3}, [%4];"
                 : "=r"(r0), "=r"(r1), "=r"(r2), "=r"(r3) : "r"(a));
}
__device__ __forceinline__ void mma16816(float* d,
                                         unsigned a0, unsigned a1, unsigned a2, unsigned a3,
                                         unsigned b0, unsigned b1) {
    asm volatile(
        "mma.sync.aligned.m16n8k16.row.col.f32.f16.f16.f32 "
        "{%0,%1,%2,%3}, {%4,%5,%6,%7}, {%8,%9}, {%0,%1,%2,%3};"
        : "+f"(d[0]), "+f"(d[1]), "+f"(d[2]), "+f"(d[3])
        : "r"(a0), "r"(a1), "r"(a2), "r"(a3), "r"(b0), "r"(b1));
}

// ---------------------------------------------------------------------------
// Fused attention via dense HMMA.
// Grid (2 j-halves, 64 row-blocks of M=128), 512 threads (16 warps).
// P-build mapping (coalesced adj): warp w owns rows 8w..8w+7; lane l owns
// j-chunk [l*4, l*4+4). Each warp LDG.128 reads 512B contiguous of one adj
// row -> 4 L1 wavefronts (was 32). Per-lane zv[8] partials, reduced once at
// the end. MMA warp tiling unchanged (16 rows x 64 cols per warp).
// ---------------------------------------------------------------------------
#define NTILES 32
#define LDH 136                         // padded row length (halves)
#define HT_BYTES (128 * LDH * 2)        // 34816
#define ATTN_SMEM (4 * HT_BYTES)        // HT0 HT1 P0 P1 = 139264

__global__ void __launch_bounds__(512, 1) attn_kernel(
    const float* __restrict__ adj, const __half* __restrict__ hTg,
    const float* __restrict__ s_src, const float* __restrict__ s_dst,
    const float* __restrict__ p_ab, const float* __restrict__ p_gmax,
    float* __restrict__ accA, float* __restrict__ accB,
    float* __restrict__ zA, float* __restrict__ zB)
{
    extern __shared__ char sm[];
    const unsigned smb = (unsigned)__cvta_generic_to_shared(sm);
    const unsigned HT0 = smb, HT1 = smb + HT_BYTES;
    const unsigned P0 = smb + 2 * HT_BYTES, P1 = smb + 3 * HT_BYTES;

    const int tid = threadIdx.x, wid = tid >> 5, lane = tid & 31;
    const int half = blockIdx.x, r0 = blockIdx.y * 128;
    const int j0 = half * (N_NODES / 2);
    float* accbuf = half ? accB : accA;
    float* zbuf   = half ? zB  : zA;

    const float ab   = *p_ab;
    const float gmax = *p_gmax;

    // per-warp row constants (rows 8*wid .. 8*wid+7)
    float si8[8], mi8[8], zv[8];
#pragma unroll
    for (int v = 0; v < 8; v++) {
        float sv = s_src[r0 + 8 * wid + v];
        si8[v] = sv;
        mi8[v] = leaky(sv + ab + gmax);
        zv[v] = 0.f;
    }

    // MMA warp tiling: 8 row-groups x 2 col-groups; warp = 16 rows x 64 cols
    const int wrow = (wid & 7) * 16;
    const int wcol = (wid >> 3) * 64;
    const unsigned a_off = (unsigned)(wrow + (lane & 15)) * (LDH * 2)
                         + (unsigned)((lane >> 4) * 8) * 2;
    const unsigned b_off = (unsigned)(wcol + (lane & 7) + ((lane >> 4) << 3)) * (LDH * 2)
                         + (unsigned)(((lane >> 3) & 1) << 3) * 2;

    float acc[8][4];
#pragma unroll
    for (int f = 0; f < 8; f++)
#pragma unroll
        for (int c = 0; c < 4; c++) acc[f][c] = 0.f;

    // coalesced adj base: warp w, lane l -> row 8w+v, floats [l*4, l*4+4)
    const float* abase = adj + (size_t)(r0 + 8 * wid) * N_NODES + j0 + lane * 4;

    auto load_hT = [&](int tile, unsigned Hb) {
#pragma unroll
        for (int i = 0; i < 4; i++) {
            int ch = tid + i * 512;
            int c = ch >> 4, u = ch & 15;
            const __half* src = hTg + (size_t)c * N_NODES + j0 + tile * 128 + u * 8;
            unsigned ad = Hb + (unsigned)c * (LDH * 2) + (unsigned)u * 16;
            asm volatile("cp.async.ca.shared.global [%0], [%1], 16;"
                         :: "r"(ad), "l"(src));
        }
    };

    // prologue: hT tile 0 + adj tile 0
    float4 av[8];
    load_hT(0, HT0);
    asm volatile("cp.async.commit_group;" ::: "memory");
#pragma unroll
    for (int v = 0; v < 8; v++)
        av[v] = *reinterpret_cast<const float4*>(abase + (size_t)v * N_NODES);

    for (int k = 0; k < NTILES; k++) {
        const unsigned Pb = (k & 1) ? P1 : P0;
        const unsigned Hb = (k & 1) ? HT1 : HT0;

        // ---- build P(k): each lane writes its 4-j chunk of 8 rows ----
        float4 t = *reinterpret_cast<const float4*>(s_dst + j0 + k * 128 + lane * 4);
#pragma unroll
        for (int v = 0; v < 8; v++) {
            float4 a = av[v];
            unsigned lo = 0u, hi = 0u;
            if (a.x >= 0.5f) { float w = __expf(leaky(si8[v] + t.x + ab) - mi8[v]);
                zv[v] += w; lo  = (unsigned)__half_as_ushort(__float2half_rn(w)); }
            if (a.y >= 0.5f) { float w = __expf(leaky(si8[v] + t.y + ab) - mi8[v]);
                zv[v] += w; lo |= (unsigned)__half_as_ushort(__float2half_rn(w)) << 16; }
            if (a.z >= 0.5f) { float w = __expf(leaky(si8[v] + t.z + ab) - mi8[v]);
                zv[v] += w; hi  = (unsigned)__half_as_ushort(__float2half_rn(w)); }
            if (a.w >= 0.5f) { float w = __expf(leaky(si8[v] + t.w + ab) - mi8[v]);
                zv[v] += w; hi |= (unsigned)__half_as_ushort(__float2half_rn(w)) << 16; }
            unsigned ad = Pb + (unsigned)(8 * wid + v) * (LDH * 2) + (unsigned)lane * 8;
            asm volatile("st.shared.v2.b32 [%0], {%1,%2};"
                         :: "r"(ad), "r"(lo), "r"(hi) : "memory");
        }

        // ---- wait hT(k), make P visible ----
        asm volatile("cp.async.wait_group 0;" ::: "memory");
        __syncthreads();

        // ---- prefetch tile k+1 (hT via cp.async, adj into regs) ----
        if (k + 1 < NTILES) {
            load_hT(k + 1, (k & 1) ? HT0 : HT1);
            asm volatile("cp.async.commit_group;" ::: "memory");
#pragma unroll
            for (int v = 0; v < 8; v++)
                av[v] = *reinterpret_cast<const float4*>(
                    abase + (size_t)v * N_NODES + (k + 1) * 128);
        }

        // ---- dense mma over this tile ----
#pragma unroll
        for (int ks = 0; ks < 8; ks++) {
            unsigned a0, a1, a2, a3;
            ldsm_x4(a0, a1, a2, a3, Pb + a_off + (unsigned)ks * 32);
#pragma unroll
            for (int nb = 0; nb < 4; nb++) {
                unsigned b0, b1, b2, b3;
                ldsm_x4(b0, b1, b2, b3,
                        Hb + b_off + (unsigned)nb * 16 * (LDH * 2) + (unsigned)ks * 32);
                mma16816(acc[nb * 2],     a0, a1, a2, a3, b0, b1);
                mma16816(acc[nb * 2 + 1], a0, a1, a2, a3, b2, b3);
            }
        }
    }

    // ---- epilogue: unnormalized acc to global ----
#pragma unroll
    for (int f = 0; f < 8; f++) {
        int n0 = wcol + f * 8 + (lane & 3) * 2;
        int rr = r0 + wrow + (lane >> 2);
        *reinterpret_cast<float2*>(&accbuf[(size_t)rr * 128 + n0]) =
            make_float2(acc[f][0], acc[f][1]);
        *reinterpret_cast<float2*>(&accbuf[(size_t)(rr + 8) * 128 + n0]) =
            make_float2(acc[f][2], acc[f][3]);
    }
    // ---- z: per-row reduction of per-lane partials (once) ----
#pragma unroll
    for (int v = 0; v < 8; v++) {
        float zz = zv[v];
#pragma unroll
        for (int o = 16; o; o >>= 1)
            zz += __shfl_xor_sync(0xffffffffu, zz, o);
        if (lane == 0) zbuf[r0 + 8 * wid + v] = zz;
    }
}

// ---------------------------------------------------------------------------
// out = leaky((accA + accB) / (zA + zB))
// ---------------------------------------------------------------------------
__global__ void __launch_bounds__(256) combine_kernel(
    const float* __restrict__ a, const float* __restrict__ b,
    const float* __restrict__ za, const float* __restrict__ zb,
    float* __restrict__ out)
{
    int idx = blockIdx.x * 256 + threadIdx.x;
    int row = idx >> 5;
    float inv = 1.f / (za[row] + zb[row]);
    float4 x = reinterpret_cast<const float4*>(a)[idx];
    float4 y = reinterpret_cast<const float4*>(b)[idx];
    float4 o;
    o.x = leaky((x.x + y.x) * inv);
    o.y = leaky((x.y + y.y) * inv);
    o.z = leaky((x.z + y.z) * inv);
    o.w = leaky((x.w + y.w) * inv);
    reinterpret_cast<float4*>(out)[idx] = o;
}

// ---------------------------------------------------------------------------
extern "C" void kernel_launch(void* const* d_in, const int* in_sizes, int n_in,
                              void* d_out, int out_size)
{
    const float* nodes = (const float*)d_in[0];
    const float* adj   = (const float*)d_in[1];
    const float* W1    = (const float*)d_in[2];
    const float* b1    = (const float*)d_in[3];
    const float* W2    = (const float*)d_in[4];
    const float* b2    = (const float*)d_in[5];
    const float* W3    = (const float*)d_in[6];
    const float* b3    = (const float*)d_in[7];
    const float* W4    = (const float*)d_in[8];
    const float* b4    = (const float*)d_in[9];
    const float* a_w   = (const float*)d_in[10];
    const float* a_b   = (const float*)d_in[11];
    float* out = (float*)d_out;

    float *pA, *pB, *pH, *pSrc, *pDst, *pZA, *pZB, *pGM;
    __half* pHT;
    cudaGetSymbolAddress((void**)&pA,  g_bufA);
    cudaGetSymbolAddress((void**)&pB,  g_bufB);
    cudaGetSymbolAddress((void**)&pH,  g_h);
    cudaGetSymbolAddress((void**)&pHT, g_hT);
    cudaGetSymbolAddress((void**)&pSrc, g_src);
    cudaGetSymbolAddress((void**)&pDst, g_dst);
    cudaGetSymbolAddress((void**)&pZA, g_zA);
    cudaGetSymbolAddress((void**)&pZB, g_zB);
    cudaGetSymbolAddress((void**)&pGM, g_gmax);

    // 4-layer MLP
    gemm_kernel<<<512, 256>>>(nodes, W1, b1, pA, 256, 1);
    gemm_kernel<<<512, 256>>>(pA,    W2, b2, pB, 128, 1);
    gemm_kernel<<<512, 256>>>(pB,    W3, b3, pA, 128, 1);
    gemm_kernel<<<512, 256>>>(pA,    W4, b4, pH, 128, 0);

    // h -> hT (fp16), scores, global max bound
    transpose_kernel<<<dim3(256, 4), 256>>>(pH, pHT);
    score_kernel<<<1024, 256>>>(pH, a_w, pSrc, pDst);
    gmax_kernel<<<1, 256>>>(pDst, pGM);

    // fused attention via dense HMMA
    cudaFuncSetAttribute(attn_kernel,
                         cudaFuncAttributeMaxDynamicSharedMemorySize, ATTN_SMEM);
    dim3 agrid(2, 64);
    attn_kernel<<<agrid, 512, ATTN_SMEM>>>(
        adj, pHT, pSrc, pDst, a_b, pGM, pA, pB, pZA, pZB);

    // normalize + activation
    combine_kernel<<<1024, 256>>>(pA, pB, pZA, pZB, out);
}